// round 10
// baseline (speedup 1.0000x reference)
#include <cuda_runtime.h>
#include <mma.h>
#include <cstdint>

using namespace nvcuda;

#define N_NODES 50000
#define N_PAD   50048
#define N_EDGES 800000
#define HID 64
#define N_CLS 16
#define MAX_DEG 64

// Scratch (device globals — no allocation allowed)
__device__ int   g_cnt[N_NODES];
__device__ int   g_adj[N_NODES * MAX_DEG];
__device__ __align__(16) float g_mean[N_NODES * HID];
__device__ __align__(16) float g_h[N_PAD * HID];
__device__ __align__(16) float g_p[N_PAD * N_CLS];
__device__ __align__(16) float g_pm[N_NODES * N_CLS];
// Pre-rounded tf32 weights
__device__ __align__(16) float g_w1[128 * 64];    // rows 0..63 = W1l, 64..127 = W1r
__device__ __align__(16) float g_w2l[64 * 16];
__device__ __align__(16) float g_w2r[64 * 16];

// ---------------------------------------------------------------------------
// Init: zero degree counters + round weights to tf32 (one kernel, idempotent)
// ---------------------------------------------------------------------------
__global__ void init_k(const float* __restrict__ W1l, const float* __restrict__ W1r,
                       const float* __restrict__ W2l, const float* __restrict__ W2r) {
    int i = blockIdx.x * blockDim.x + threadIdx.x;
    if (i < N_NODES) g_cnt[i] = 0;
    if (i < 4096) {
        g_w1[i]        = wmma::__float_to_tf32(W1l[i]);
        g_w1[4096 + i] = wmma::__float_to_tf32(W1r[i]);
    }
    if (i < 1024) {
        g_w2l[i] = wmma::__float_to_tf32(W2l[i]);
        g_w2r[i] = wmma::__float_to_tf32(W2r[i]);
    }
}

__global__ void fill_k(const int* __restrict__ ei) {
    int e = blockIdx.x * blockDim.x + threadIdx.x;
    if (e >= N_EDGES) return;
    int s = ei[e];
    int d = ei[N_EDGES + e];
    if ((unsigned)s >= N_NODES || (unsigned)d >= N_NODES) return;
    int pos = atomicAdd(&g_cnt[d], 1);
    if (pos < MAX_DEG) g_adj[d * MAX_DEG + pos] = s;
}

// ---------------------------------------------------------------------------
// Mean gather, split x2: 2*W4 threads per node. Slot g in {0,1} handles half
// of each int4 index batch; shfl_xor(W4) combines; g==0 lanes write.
// SEL 0: src = x,   dst = g_mean, W4 = 16 (64-float rows)
// SEL 1: src = g_p, dst = g_pm,   W4 = 4  (16-float rows)
// ---------------------------------------------------------------------------
template<int SEL, int LOG_W4>
__global__ void gather_mean_k(const float4* __restrict__ xin) {
    constexpr int W4 = 1 << LOG_W4;
    const float4* src = (SEL == 0) ? xin : reinterpret_cast<const float4*>(g_p);
    float4* dst = (SEL == 0) ? reinterpret_cast<float4*>(g_mean)
                             : reinterpret_cast<float4*>(g_pm);
    int t = blockIdx.x * blockDim.x + threadIdx.x;
    int node = t >> (LOG_W4 + 1);
    int sub  = t & (2 * W4 - 1);
    int g    = sub >> LOG_W4;
    int f    = sub & (W4 - 1);
    if (node >= N_NODES) return;
    int c = g_cnt[node];
    int cl = min(c, MAX_DEG);
    const int4* row4 = reinterpret_cast<const int4*>(g_adj + (size_t)node * MAX_DEG);
    float4 a0 = make_float4(0.f,0.f,0.f,0.f), a1 = a0;
    int nfull = cl >> 2;
#pragma unroll 2
    for (int j4 = 0; j4 < nfull; j4++) {
        int4 idx = __ldg(row4 + j4);
        int i0 = g ? idx.z : idx.x;
        int i1 = g ? idx.w : idx.y;
        float4 v0 = __ldg(src + (((size_t)i0) << LOG_W4) + f);
        float4 v1 = __ldg(src + (((size_t)i1) << LOG_W4) + f);
        a0.x += v0.x; a0.y += v0.y; a0.z += v0.z; a0.w += v0.w;
        a1.x += v1.x; a1.y += v1.y; a1.z += v1.z; a1.w += v1.w;
    }
    for (int j = nfull * 4 + g; j < cl; j += 2) {
        int s = __ldg(g_adj + (size_t)node * MAX_DEG + j);
        float4 v = __ldg(src + (((size_t)s) << LOG_W4) + f);
        a0.x += v.x; a0.y += v.y; a0.z += v.z; a0.w += v.w;
    }
    float4 r;
    r.x = a0.x + a1.x; r.y = a0.y + a1.y; r.z = a0.z + a1.z; r.w = a0.w + a1.w;
    r.x += __shfl_xor_sync(0xffffffff, r.x, W4);
    r.y += __shfl_xor_sync(0xffffffff, r.y, W4);
    r.z += __shfl_xor_sync(0xffffffff, r.z, W4);
    r.w += __shfl_xor_sync(0xffffffff, r.w, W4);
    if (g == 0) {
        float invd = 1.0f / fmaxf((float)c, 1.0f);
        r.x *= invd; r.y *= invd; r.z *= invd; r.w *= invd;
        dst[((size_t)node << LOG_W4) + f] = r;
    }
}

// ---------------------------------------------------------------------------
// Layer 1 (one 64-node tile per block, B register-cached, no cvt):
//   h = relu([mean||x] @ g_w1 + b1);  p = h @ g_w2l
// ---------------------------------------------------------------------------
__global__ void __launch_bounds__(128)
layer1_k(const float* __restrict__ x, const float* __restrict__ b1) {
    __shared__ float sA[64][132];
    __shared__ float sH[64][68];
    __shared__ float sb1[64];

    int tid = threadIdx.x, warp = tid >> 5;
    int n0 = warp * 16;
    int node0 = blockIdx.x * 64;
    if (tid < 64) sb1[tid] = b1[tid];

    // Cache this warp's 16 B fragments (whole K=128) in registers.
    wmma::fragment<wmma::matrix_b, 16, 16, 8, wmma::precision::tf32, wmma::row_major> BF[16];
#pragma unroll
    for (int kk = 0; kk < 16; kk++)
        wmma::load_matrix_sync(BF[kk], g_w1 + (size_t)kk * 8 * 64 + n0, 64);

    // Stage A = tf32([mean || x]), zero-filled past N_NODES
    const float4* m4 = reinterpret_cast<const float4*>(g_mean);
    const float4* x4 = reinterpret_cast<const float4*>(x);
    for (int i = tid; i < 2048; i += 128) {
        int r = i >> 5, c4 = i & 31;
        int node = node0 + r;
        float4 v = make_float4(0.f, 0.f, 0.f, 0.f);
        if (node < N_NODES)
            v = (c4 < 16) ? m4[(size_t)node * 16 + c4]
                          : x4[(size_t)node * 16 + (c4 - 16)];
        v.x = wmma::__float_to_tf32(v.x);
        v.y = wmma::__float_to_tf32(v.y);
        v.z = wmma::__float_to_tf32(v.z);
        v.w = wmma::__float_to_tf32(v.w);
        *reinterpret_cast<float4*>(&sA[r][c4 * 4]) = v;
    }
    __syncthreads();

    // Main GEMM: warp w computes cols [n0, n0+16) for all 64 rows
    wmma::fragment<wmma::accumulator, 16, 16, 8, float> acc[4];
#pragma unroll
    for (int m = 0; m < 4; m++) wmma::fill_fragment(acc[m], 0.f);
#pragma unroll
    for (int kk = 0; kk < 16; kk++) {
#pragma unroll
        for (int m = 0; m < 4; m++) {
            wmma::fragment<wmma::matrix_a, 16, 16, 8, wmma::precision::tf32, wmma::row_major> a;
            wmma::load_matrix_sync(a, &sA[m * 16][kk * 8], 132);
            wmma::mma_sync(acc[m], a, BF[kk], acc[m]);
        }
    }
#pragma unroll
    for (int m = 0; m < 4; m++)
        wmma::store_matrix_sync(&sH[m * 16][n0], acc[m], 68, wmma::mem_row_major);
    __syncthreads();

    // Bias + relu + round; write g_h
    for (int i = tid; i < 4096; i += 128) {
        int r = i >> 6, c = i & 63;
        float v = wmma::__float_to_tf32(fmaxf(sH[r][c] + sb1[c], 0.f));
        sH[r][c] = v;
        int node = node0 + r;
        if (node < N_NODES) g_h[(size_t)node * 64 + c] = v;
    }
    __syncthreads();

    // p = h @ W2l : warp w handles rows [16w, 16w+16); direct store to padded g_p
    {
        int m0 = warp * 16;
        wmma::fragment<wmma::accumulator, 16, 16, 8, float> acc2;
        wmma::fill_fragment(acc2, 0.f);
#pragma unroll
        for (int kk = 0; kk < 8; kk++) {
            wmma::fragment<wmma::matrix_a, 16, 16, 8, wmma::precision::tf32, wmma::row_major> a2;
            wmma::load_matrix_sync(a2, &sH[m0][kk * 8], 68);
            wmma::fragment<wmma::matrix_b, 16, 16, 8, wmma::precision::tf32, wmma::row_major> b2;
            wmma::load_matrix_sync(b2, g_w2l + (size_t)kk * 8 * 16, 16);
            wmma::mma_sync(acc2, a2, b2, acc2);
        }
        wmma::store_matrix_sync(g_p + (size_t)(node0 + m0) * 16, acc2, 16,
                                wmma::mem_row_major);
    }
}

// ---------------------------------------------------------------------------
// Final: out = g_pm + h @ W2r + b2. No cvt (inputs pre-rounded).
// ---------------------------------------------------------------------------
__global__ void __launch_bounds__(128)
final_k(const float* __restrict__ b2, float* __restrict__ out) {
    __shared__ float sO[64][16];
    __shared__ float sb[16];
    int tid = threadIdx.x, warp = tid >> 5, lane = tid & 31;
    int node0 = blockIdx.x * 64;
    if (tid < 16) sb[tid] = b2[tid];
    __syncthreads();

    int m0 = warp * 16;
    wmma::fragment<wmma::accumulator, 16, 16, 8, float> acc;
    wmma::fill_fragment(acc, 0.f);
#pragma unroll
    for (int kk = 0; kk < 8; kk++) {
        wmma::fragment<wmma::matrix_a, 16, 16, 8, wmma::precision::tf32, wmma::row_major> a;
        wmma::load_matrix_sync(a, g_h + (size_t)(node0 + m0) * 64 + kk * 8, 64);
        wmma::fragment<wmma::matrix_b, 16, 16, 8, wmma::precision::tf32, wmma::row_major> b;
        wmma::load_matrix_sync(b, g_w2r + (size_t)kk * 8 * 16, 16);
        wmma::mma_sync(acc, a, b, acc);
    }
    wmma::store_matrix_sync(&sO[m0][0], acc, 16, wmma::mem_row_major);
    __syncwarp();

    for (int i = lane; i < 256; i += 32) {
        int r = i >> 4, c = i & 15;
        int node = node0 + m0 + r;
        if (node < N_NODES)
            out[(size_t)node * 16 + c] = sO[m0 + r][c] + g_pm[(size_t)node * 16 + c] + sb[c];
    }
}

// ---------------------------------------------------------------------------
extern "C" void kernel_launch(void* const* d_in, const int* in_sizes, int n_in,
                              void* d_out, int out_size) {
    const float* x   = (const float*)d_in[0];
    const int*   ei  = (const int*)d_in[1];     // int32 (JAX x64 disabled)
    const float* W1l = (const float*)d_in[2];
    const float* b1  = (const float*)d_in[3];
    const float* W1r = (const float*)d_in[4];
    const float* W2l = (const float*)d_in[5];
    const float* b2  = (const float*)d_in[6];
    const float* W2r = (const float*)d_in[7];
    float* out = (float*)d_out;

    const int NBLK = (N_NODES + 63) / 64;   // 782

    init_k<<<(N_NODES + 255) / 256, 256>>>(W1l, W1r, W2l, W2r);
    fill_k<<<(N_EDGES + 255) / 256, 256>>>(ei);
    gather_mean_k<0, 4><<<(N_NODES * 32 + 255) / 256, 256>>>((const float4*)x);
    layer1_k<<<NBLK, 128>>>(x, b1);
    gather_mean_k<1, 2><<<(N_NODES * 8 + 255) / 256, 256>>>(nullptr);
    final_k<<<NBLK, 128>>>(b2, out);
}

// round 11
// speedup vs baseline: 1.0789x; 1.0789x over previous
#include <cuda_runtime.h>
#include <mma.h>
#include <cstdint>

using namespace nvcuda;

#define N_NODES 50000
#define N_PAD   50048
#define N_EDGES 800000
#define HID 64
#define N_CLS 16
#define MAX_DEG 64

// Scratch (device globals — no allocation allowed)
__device__ int   g_cnt[N_NODES];
__device__ int   g_adj[N_NODES * MAX_DEG];
__device__ __align__(16) float g_mean[N_NODES * HID];
__device__ __align__(16) float g_h[N_PAD * HID];
__device__ __align__(16) float g_p[N_PAD * N_CLS];
__device__ __align__(16) float g_pm[N_NODES * N_CLS];
// Pre-rounded tf32 weights
__device__ __align__(16) float g_w1[128 * 64];    // rows 0..63 = W1l, 64..127 = W1r
__device__ __align__(16) float g_w2l[64 * 16];
__device__ __align__(16) float g_w2r[64 * 16];

// ---------------------------------------------------------------------------
// Init: zero degree counters + round weights to tf32 (one kernel, idempotent)
// ---------------------------------------------------------------------------
__global__ void init_k(const float* __restrict__ W1l, const float* __restrict__ W1r,
                       const float* __restrict__ W2l, const float* __restrict__ W2r) {
    int i = blockIdx.x * blockDim.x + threadIdx.x;
    if (i < N_NODES) g_cnt[i] = 0;
    if (i < 4096) {
        g_w1[i]        = wmma::__float_to_tf32(W1l[i]);
        g_w1[4096 + i] = wmma::__float_to_tf32(W1r[i]);
    }
    if (i < 1024) {
        g_w2l[i] = wmma::__float_to_tf32(W2l[i]);
        g_w2r[i] = wmma::__float_to_tf32(W2r[i]);
    }
}

__global__ void fill_k(const int* __restrict__ ei) {
    int e = blockIdx.x * blockDim.x + threadIdx.x;
    if (e >= N_EDGES) return;
    int s = ei[e];
    int d = ei[N_EDGES + e];
    if ((unsigned)s >= N_NODES || (unsigned)d >= N_NODES) return;
    int pos = atomicAdd(&g_cnt[d], 1);
    if (pos < MAX_DEG) g_adj[d * MAX_DEG + pos] = s;
}

// ---------------------------------------------------------------------------
// Mean gather, split x2: 2*W4 threads per node (R10 version).
// SEL 0: src = x,   dst = g_mean, W4 = 16;  SEL 1: src = g_p, dst = g_pm, W4 = 4
// ---------------------------------------------------------------------------
template<int SEL, int LOG_W4>
__global__ void gather_mean_k(const float4* __restrict__ xin) {
    constexpr int W4 = 1 << LOG_W4;
    const float4* src = (SEL == 0) ? xin : reinterpret_cast<const float4*>(g_p);
    float4* dst = (SEL == 0) ? reinterpret_cast<float4*>(g_mean)
                             : reinterpret_cast<float4*>(g_pm);
    int t = blockIdx.x * blockDim.x + threadIdx.x;
    int node = t >> (LOG_W4 + 1);
    int sub  = t & (2 * W4 - 1);
    int g    = sub >> LOG_W4;
    int f    = sub & (W4 - 1);
    if (node >= N_NODES) return;
    int c = g_cnt[node];
    int cl = min(c, MAX_DEG);
    const int4* row4 = reinterpret_cast<const int4*>(g_adj + (size_t)node * MAX_DEG);
    float4 a0 = make_float4(0.f,0.f,0.f,0.f), a1 = a0;
    int nfull = cl >> 2;
#pragma unroll 2
    for (int j4 = 0; j4 < nfull; j4++) {
        int4 idx = __ldg(row4 + j4);
        int i0 = g ? idx.z : idx.x;
        int i1 = g ? idx.w : idx.y;
        float4 v0 = __ldg(src + (((size_t)i0) << LOG_W4) + f);
        float4 v1 = __ldg(src + (((size_t)i1) << LOG_W4) + f);
        a0.x += v0.x; a0.y += v0.y; a0.z += v0.z; a0.w += v0.w;
        a1.x += v1.x; a1.y += v1.y; a1.z += v1.z; a1.w += v1.w;
    }
    for (int j = nfull * 4 + g; j < cl; j += 2) {
        int s = __ldg(g_adj + (size_t)node * MAX_DEG + j);
        float4 v = __ldg(src + (((size_t)s) << LOG_W4) + f);
        a0.x += v.x; a0.y += v.y; a0.z += v.z; a0.w += v.w;
    }
    float4 r;
    r.x = a0.x + a1.x; r.y = a0.y + a1.y; r.z = a0.z + a1.z; r.w = a0.w + a1.w;
    r.x += __shfl_xor_sync(0xffffffff, r.x, W4);
    r.y += __shfl_xor_sync(0xffffffff, r.y, W4);
    r.z += __shfl_xor_sync(0xffffffff, r.z, W4);
    r.w += __shfl_xor_sync(0xffffffff, r.w, W4);
    if (g == 0) {
        float invd = 1.0f / fmaxf((float)c, 1.0f);
        r.x *= invd; r.y *= invd; r.z *= invd; r.w *= invd;
        dst[((size_t)node << LOG_W4) + f] = r;
    }
}

// ---------------------------------------------------------------------------
// Layer 1 (R8 structure, zero cvt, in-place h, low regs):
//   h = relu([mean||x] @ g_w1 + b1);  p = h @ g_w2l
// 128 threads = 4 warps; one 64-node tile per block; warp w owns n-tile w.
// B fragments straight from pre-rounded global (L1-resident).
// ---------------------------------------------------------------------------
__global__ void __launch_bounds__(128)
layer1_k(const float* __restrict__ x, const float* __restrict__ b1) {
    __shared__ float sA[64][132];   // [mean||x] rounded; later h in cols 0..63
    __shared__ float sb1[64];

    int tid = threadIdx.x, warp = tid >> 5;
    int n0 = warp * 16;
    int node0 = blockIdx.x * 64;
    if (tid < 64) sb1[tid] = b1[tid];

    // Stage A = tf32([mean || x]), zero-filled past N_NODES
    const float4* m4 = reinterpret_cast<const float4*>(g_mean);
    const float4* x4 = reinterpret_cast<const float4*>(x);
    for (int i = tid; i < 2048; i += 128) {
        int r = i >> 5, c4 = i & 31;
        int node = node0 + r;
        float4 v = make_float4(0.f, 0.f, 0.f, 0.f);
        if (node < N_NODES)
            v = (c4 < 16) ? m4[(size_t)node * 16 + c4]
                          : x4[(size_t)node * 16 + (c4 - 16)];
        v.x = wmma::__float_to_tf32(v.x);
        v.y = wmma::__float_to_tf32(v.y);
        v.z = wmma::__float_to_tf32(v.z);
        v.w = wmma::__float_to_tf32(v.w);
        *reinterpret_cast<float4*>(&sA[r][c4 * 4]) = v;
    }
    __syncthreads();

    // Main GEMM: warp w computes cols [n0, n0+16) for all 64 rows
    wmma::fragment<wmma::accumulator, 16, 16, 8, float> acc[4];
#pragma unroll
    for (int m = 0; m < 4; m++) wmma::fill_fragment(acc[m], 0.f);
#pragma unroll
    for (int kk = 0; kk < 16; kk++) {
        wmma::fragment<wmma::matrix_b, 16, 16, 8, wmma::precision::tf32, wmma::row_major> b;
        wmma::load_matrix_sync(b, g_w1 + (size_t)kk * 8 * 64 + n0, 64);
#pragma unroll
        for (int m = 0; m < 4; m++) {
            wmma::fragment<wmma::matrix_a, 16, 16, 8, wmma::precision::tf32, wmma::row_major> a;
            wmma::load_matrix_sync(a, &sA[m * 16][kk * 8], 132);
            wmma::mma_sync(acc[m], a, b, acc[m]);
        }
    }
    __syncthreads();   // all warps done READING sA before in-place stores

#pragma unroll
    for (int m = 0; m < 4; m++)
        wmma::store_matrix_sync(&sA[m * 16][n0], acc[m], 132, wmma::mem_row_major);
    __syncthreads();

    // Bias + relu + round in place (cols 0..63); write g_h
    for (int i = tid; i < 4096; i += 128) {
        int r = i >> 6, c = i & 63;
        float v = wmma::__float_to_tf32(fmaxf(sA[r][c] + sb1[c], 0.f));
        sA[r][c] = v;
        int node = node0 + r;
        if (node < N_NODES) g_h[(size_t)node * 64 + c] = v;
    }
    __syncthreads();

    // p = h @ W2l : warp w handles rows [16w, 16w+16); direct store to padded g_p
    {
        int m0 = warp * 16;
        wmma::fragment<wmma::accumulator, 16, 16, 8, float> acc2;
        wmma::fill_fragment(acc2, 0.f);
#pragma unroll
        for (int kk = 0; kk < 8; kk++) {
            wmma::fragment<wmma::matrix_a, 16, 16, 8, wmma::precision::tf32, wmma::row_major> a2;
            wmma::load_matrix_sync(a2, &sA[m0][kk * 8], 132);
            wmma::fragment<wmma::matrix_b, 16, 16, 8, wmma::precision::tf32, wmma::row_major> b2;
            wmma::load_matrix_sync(b2, g_w2l + (size_t)kk * 8 * 16, 16);
            wmma::mma_sync(acc2, a2, b2, acc2);
        }
        wmma::store_matrix_sync(g_p + (size_t)(node0 + m0) * 16, acc2, 16,
                                wmma::mem_row_major);
    }
}

// ---------------------------------------------------------------------------
// Final: out = g_pm + h @ W2r + b2. No cvt (inputs pre-rounded).
// ---------------------------------------------------------------------------
__global__ void __launch_bounds__(128)
final_k(const float* __restrict__ b2, float* __restrict__ out) {
    __shared__ float sO[64][16];
    __shared__ float sb[16];
    int tid = threadIdx.x, warp = tid >> 5, lane = tid & 31;
    int node0 = blockIdx.x * 64;
    if (tid < 16) sb[tid] = b2[tid];
    __syncthreads();

    int m0 = warp * 16;
    wmma::fragment<wmma::accumulator, 16, 16, 8, float> acc;
    wmma::fill_fragment(acc, 0.f);
#pragma unroll
    for (int kk = 0; kk < 8; kk++) {
        wmma::fragment<wmma::matrix_a, 16, 16, 8, wmma::precision::tf32, wmma::row_major> a;
        wmma::load_matrix_sync(a, g_h + (size_t)(node0 + m0) * 64 + kk * 8, 64);
        wmma::fragment<wmma::matrix_b, 16, 16, 8, wmma::precision::tf32, wmma::row_major> b;
        wmma::load_matrix_sync(b, g_w2r + (size_t)kk * 8 * 16, 16);
        wmma::mma_sync(acc, a, b, acc);
    }
    wmma::store_matrix_sync(&sO[m0][0], acc, 16, wmma::mem_row_major);
    __syncwarp();

    for (int i = lane; i < 256; i += 32) {
        int r = i >> 4, c = i & 15;
        int node = node0 + m0 + r;
        if (node < N_NODES)
            out[(size_t)node * 16 + c] = sO[m0 + r][c] + g_pm[(size_t)node * 16 + c] + sb[c];
    }
}

// ---------------------------------------------------------------------------
extern "C" void kernel_launch(void* const* d_in, const int* in_sizes, int n_in,
                              void* d_out, int out_size) {
    const float* x   = (const float*)d_in[0];
    const int*   ei  = (const int*)d_in[1];     // int32 (JAX x64 disabled)
    const float* W1l = (const float*)d_in[2];
    const float* b1  = (const float*)d_in[3];
    const float* W1r = (const float*)d_in[4];
    const float* W2l = (const float*)d_in[5];
    const float* b2  = (const float*)d_in[6];
    const float* W2r = (const float*)d_in[7];
    float* out = (float*)d_out;

    const int NBLK = (N_NODES + 63) / 64;   // 782

    init_k<<<(N_NODES + 255) / 256, 256>>>(W1l, W1r, W2l, W2r);
    fill_k<<<(N_EDGES + 255) / 256, 256>>>(ei);
    gather_mean_k<0, 4><<<(N_NODES * 32 + 255) / 256, 256>>>((const float4*)x);
    layer1_k<<<NBLK, 128>>>(x, b1);
    gather_mean_k<1, 2><<<(N_NODES * 8 + 255) / 256, 256>>>(nullptr);
    final_k<<<NBLK, 128>>>(b2, out);
}